// round 13
// baseline (speedup 1.0000x reference)
#include <cuda_runtime.h>
#include <cuda_bf16.h>
#include <cuda_fp16.h>
#include <cstdint>

// ---------------------------------------------------------------------------
// BidirectionalMambaLayer — Round 13: atomic-free GEMM epilogues.
// out_proj = one concat-K GEMM (dirs merged into K), split-K partials +
// deterministic add; x_proj split-K partials + fixed-order reduce.
// GEMM core = round 12 (fp16 m16n8k16, BK=64, fragment double-buffer),
// STG=2 / 73.7KB smem (2 CTAs/SM).
// ---------------------------------------------------------------------------

#define SEQL   1024
#define NB     2
#define MTOT   (NB * SEQL)
#define DMODEL 768
#define DINNER 1536
#define DSTATE 16
#define DTRANK 48
#define DCONV  4
#define XZW    (2 * DINNER)            // 3072
#define XDBLW  (DTRANK + 2 * DSTATE)   // 80
#define NSPLIT 8                       // x_proj split-K count

// -------------------------- scratch (device globals) -----------------------
__device__ float  g_xz   [2][(size_t)MTOT * XZW];
__device__ float  g_u    [2][(size_t)MTOT * DINNER];  // exact (scan)
__device__ __half g_ur   [2][(size_t)MTOT * DINNER];  // fp16 (x_proj A)
__device__ float  g_xpart[2][NSPLIT][(size_t)MTOT * XDBLW]; // x_proj partials
__device__ float  g_xdbl [2][(size_t)MTOT * XDBLW];   // reduced totals
__device__ float  g_delta[2][(size_t)MTOT * DINNER];
__device__ __half g_yall [(size_t)MTOT * XZW];        // [2048,3072] ypre f|b
__device__ float  g_opart[2][(size_t)MTOT * DMODEL];  // out_proj split partials
__device__ __half g_xr   [(size_t)MTOT * DMODEL];     // fp16 x
__device__ __half g_win  [2][(size_t)XZW * DMODEL];
__device__ __half g_wxp  [2][(size_t)XDBLW * DINNER];
__device__ __half g_wdt  [2][(size_t)DINNER * DTRANK];
__device__ __half g_wcat [(size_t)DMODEL * XZW];      // [768,3072] f|b out_w

enum { HBUF_XR = 0, HBUF_UR, HBUF_YALL, HBUF_WIN, HBUF_WXP, HBUF_WCAT };

__device__ __forceinline__ __half* scratch_h(int id, int dir) {
    switch (id) {
        case HBUF_XR:   return g_xr;
        case HBUF_UR:   return g_ur[dir];
        case HBUF_YALL: return g_yall;
        case HBUF_WIN:  return g_win[dir];
        case HBUF_WXP:  return g_wxp[dir];
        case HBUF_WCAT: return g_wcat;
    }
    return nullptr;
}

__device__ __forceinline__ void cp16(uint32_t saddr, const __half* gptr, bool ok) {
    int sz = ok ? 16 : 0;
    asm volatile("cp.async.cg.shared.global [%0], [%1], 16, %2;"
                 :: "r"(saddr), "l"(gptr), "r"(sz));
}
__device__ __forceinline__ void cp_commit() { asm volatile("cp.async.commit_group;"); }
__device__ __forceinline__ void cp_wait0()  { asm volatile("cp.async.wait_group 0;"); }

__device__ __forceinline__ void ldsm_x4(uint32_t& r0, uint32_t& r1,
                                        uint32_t& r2, uint32_t& r3, uint32_t a) {
    asm volatile("ldmatrix.sync.aligned.m8n8.x4.shared.b16 {%0,%1,%2,%3}, [%4];"
                 : "=r"(r0), "=r"(r1), "=r"(r2), "=r"(r3) : "r"(a));
}

#define MMA_F16(acc, a, b)                                              \
    asm volatile(                                                       \
        "mma.sync.aligned.m16n8k16.row.col.f32.f16.f16.f32 "            \
        "{%0,%1,%2,%3}, {%4,%5,%6,%7}, {%8,%9}, {%0,%1,%2,%3};"         \
        : "+f"((acc)[0]), "+f"((acc)[1]), "+f"((acc)[2]), "+f"((acc)[3])\
        : "r"((a)[0]), "r"((a)[1]), "r"((a)[2]), "r"((a)[3]),           \
          "r"((b)[0]), "r"((b)[1]))

// ---------------------------------------------------------------------------
// fp16 mma.sync TN GEMM, BK=64, STG=2 (dynamic smem), dir-merged, split-K
// with plain stores (split-s output goes to base + s*splitStride).
// BM=BN=128, 256 threads (8 warps 2m x 4n), warp tile 64x32.
// ---------------------------------------------------------------------------
#define GBK   64
#define GSASX 72                        // 64 + 8 halves pad
#define SMEM_BK64 (2 * (128 * GSASX * 2) * 2)   // 73728 B

template<bool FLIPA1>
__global__ __launch_bounds__(256)
void gemm_h(int aId, int bId,
            float* __restrict__ Cext, float* __restrict__ Cd0, float* __restrict__ Cd1,
            long splitStride,
            int N, int K, int lda, int ldc, int nxt, int kchunk)
{
    constexpr int CPR = GBK / 8;          // 8 chunks of 16B per row
    constexpr int LIT = 128 * CPR / 256;  // 4 per matrix

    const int dir = blockIdx.z;
    const __half* A = scratch_h(aId, dir);
    const __half* W = scratch_h(bId, dir);

    const int split = blockIdx.x / nxt;
    const int bn    = (blockIdx.x - split * nxt) * 128;
    const int bm    = blockIdx.y * 128;
    const int kbeg  = split * kchunk;
    const int T     = kchunk / GBK;

    float* C = (Cext ? Cext : (dir ? Cd1 : Cd0)) + (long)split * splitStride;

    extern __shared__ __half dynsmem_h[];

    const int tid  = threadIdx.x;
    const int lane = tid & 31;
    const int warp = tid >> 5;
    const int wm   = warp >> 2;
    const int wn   = warp & 3;
    const int gr   = lane >> 2;
    const int tq   = lane & 3;

    const uint32_t stage_bytes = 128 * GSASX * 2;
    const uint32_t sAb = (uint32_t)__cvta_generic_to_shared(dynsmem_h);
    const uint32_t sBb = sAb + 2 * stage_bytes;

    const uint32_t laneA =
        ((uint32_t)((wm * 64 + (lane & 15)) * GSASX + (lane >> 4) * 8)) * 2;
    const uint32_t laneB =
        ((uint32_t)((wn * 32 + (lane & 7) + ((lane & 16) ? 8 : 0)) * GSASX +
                    ((lane & 8) ? 8 : 0))) * 2;

    int arow[LIT], aq[LIT];
    uint32_t soff[LIT];
#pragma unroll
    for (int i = 0; i < LIT; i++) {
        const int c = tid + i * 256;
        arow[i] = c / CPR;
        aq[i]   = (c - arow[i] * CPR) * 8;
        soff[i] = (uint32_t)(arow[i] * GSASX + aq[i]) * 2;
    }

    auto load_tile = [&](int t, int st) {
        const int kof = kbeg + t * GBK;
#pragma unroll
        for (int i = 0; i < LIT; i++) {
            int gm = bm + arow[i];
            if (FLIPA1 && dir) gm ^= (SEQL - 1);
            cp16(sAb + st * stage_bytes + soff[i],
                 A + (size_t)gm * lda + kof + aq[i], true);
        }
#pragma unroll
        for (int i = 0; i < LIT; i++) {
            const int wr = bn + arow[i];
            cp16(sBb + st * stage_bytes + soff[i],
                 W + (size_t)wr * K + kof + aq[i], wr < N);
        }
        cp_commit();
    };

    float acc[4][4][4];
#pragma unroll
    for (int mt = 0; mt < 4; mt++)
#pragma unroll
        for (int nt = 0; nt < 4; nt++)
#pragma unroll
            for (int r = 0; r < 4; r++) acc[mt][nt][r] = 0.f;

    load_tile(0, 0);

    for (int t = 0; t < T; t++) {
        const int st = t & 1;
        cp_wait0();
        __syncthreads();

        if (t + 1 < T) load_tile(t + 1, st ^ 1);

        const uint32_t aAddr = sAb + st * stage_bytes + laneA;
        const uint32_t bAddr = sBb + st * stage_bytes + laneB;

        uint32_t a[2][4][4], b[2][4][2];
#pragma unroll
        for (int mt = 0; mt < 4; mt++)
            ldsm_x4(a[0][mt][0], a[0][mt][1], a[0][mt][2], a[0][mt][3],
                    aAddr + (uint32_t)(mt * 16 * GSASX) * 2);
#pragma unroll
        for (int p = 0; p < 2; p++)
            ldsm_x4(b[0][2 * p][0], b[0][2 * p][1],
                    b[0][2 * p + 1][0], b[0][2 * p + 1][1],
                    bAddr + (uint32_t)(p * 16 * GSASX) * 2);

#pragma unroll
        for (int ks = 0; ks < GBK / 16; ks++) {
            const int cur = ks & 1;
            if (ks + 1 < GBK / 16) {
                const int nb = cur ^ 1;
                const uint32_t kb2 = (uint32_t)((ks + 1) * 16) * 2;
#pragma unroll
                for (int mt = 0; mt < 4; mt++)
                    ldsm_x4(a[nb][mt][0], a[nb][mt][1], a[nb][mt][2], a[nb][mt][3],
                            aAddr + (uint32_t)(mt * 16 * GSASX) * 2 + kb2);
#pragma unroll
                for (int p = 0; p < 2; p++)
                    ldsm_x4(b[nb][2 * p][0], b[nb][2 * p][1],
                            b[nb][2 * p + 1][0], b[nb][2 * p + 1][1],
                            bAddr + (uint32_t)(p * 16 * GSASX) * 2 + kb2);
            }
#pragma unroll
            for (int mt = 0; mt < 4; mt++)
#pragma unroll
                for (int nt = 0; nt < 4; nt++)
                    MMA_F16(acc[mt][nt], a[cur][mt], b[cur][nt]);
        }
    }

    // epilogue: plain stores
#pragma unroll
    for (int mt = 0; mt < 4; mt++) {
        const int m0 = bm + wm * 64 + mt * 16 + gr;
#pragma unroll
        for (int half = 0; half < 2; half++) {
            const int m = m0 + half * 8;
#pragma unroll
            for (int nt = 0; nt < 4; nt++) {
                const int nbase = bn + wn * 32 + nt * 8 + 2 * tq;
#pragma unroll
                for (int j = 0; j < 2; j++) {
                    const int n = nbase + j;
                    if (n < N)
                        C[(size_t)m * ldc + n] = acc[mt][nt][half * 2 + j];
                }
            }
        }
    }
}

// ---------------------------------------------------------------------------
// Reduce x_proj partials: xdbl[dir] = sum_{s=0..7} xpart[dir][s]  (fixed order)
// ---------------------------------------------------------------------------
__global__ void reduce_xdbl_kernel()
{
    const int dir = blockIdx.y;
    const int n4  = MTOT * XDBLW / 4;
    const int i   = blockIdx.x * blockDim.x + threadIdx.x;
    if (i >= n4) return;
    float4 s = make_float4(0.f, 0.f, 0.f, 0.f);
#pragma unroll
    for (int sp = 0; sp < NSPLIT; sp++) {
        const float4 v = ((const float4*)g_xpart[dir][sp])[i];
        s.x += v.x; s.y += v.y; s.z += v.z; s.w += v.w;
    }
    ((float4*)g_xdbl[dir])[i] = s;
}

// ---------------------------------------------------------------------------
// out = opart0 + opart1  (split boundary == dir boundary; matches old sum)
// ---------------------------------------------------------------------------
__global__ void add_out_kernel(float4* __restrict__ out4)
{
    const int n4 = MTOT * DMODEL / 4;
    const int i  = blockIdx.x * blockDim.x + threadIdx.x;
    if (i >= n4) return;
    const float4 a = ((const float4*)g_opart[0])[i];
    const float4 b = ((const float4*)g_opart[1])[i];
    out4[i] = make_float4(a.x + b.x, a.y + b.y, a.z + b.z, a.w + b.w);
}

// ---------------------------------------------------------------------------
// Fused small-K delta GEMM: delta = softplus(dt @ dt_w^T + dt_b), K=48.
// ---------------------------------------------------------------------------
#define DSASX 56    // 48 + 8 pad
__global__ __launch_bounds__(256, 2)
void gemm_delta(const float* __restrict__ dt_b0, const float* __restrict__ dt_b1)
{
    const int dir = blockIdx.z;
    const float*  Xd = g_xdbl[dir];
    const __half* W  = g_wdt[dir];
    const float*  bias = dir ? dt_b1 : dt_b0;
    float*        Cc = g_delta[dir];

    __shared__ __half sA[128 * DSASX];
    __shared__ __half sB[128 * DSASX];

    const int bn = blockIdx.x * 128;
    const int bm = blockIdx.y * 128;

    const int tid  = threadIdx.x;
    const int lane = tid & 31;
    const int warp = tid >> 5;
    const int wm   = warp >> 2;
    const int wn   = warp & 3;
    const int gr   = lane >> 2;
    const int tq   = lane & 3;

    const uint32_t sAb = (uint32_t)__cvta_generic_to_shared(sA);
    const uint32_t sBb = (uint32_t)__cvta_generic_to_shared(sB);

#pragma unroll
    for (int i = 0; i < 3; i++) {
        const int c = tid + i * 256;
        const int r = c / 6, q = (c - r * 6) * 8;
        cp16(sBb + (uint32_t)(r * DSASX + q) * 2, W + (size_t)(bn + r) * DTRANK + q, true);
    }
    cp_commit();

#pragma unroll
    for (int i = 0; i < 6; i++) {
        const int c = tid + i * 256;
        const int r = c / 12, q = (c - r * 12) * 4;
        const float4 v = *(const float4*)(Xd + (size_t)(bm + r) * XDBLW + q);
        __half2* d2 = reinterpret_cast<__half2*>(&sA[r * DSASX + q]);
        d2[0] = __floats2half2_rn(v.x, v.y);
        d2[1] = __floats2half2_rn(v.z, v.w);
    }
    cp_wait0();
    __syncthreads();

    const uint32_t laneA =
        ((uint32_t)((wm * 64 + (lane & 15)) * DSASX + (lane >> 4) * 8)) * 2;
    const uint32_t laneB =
        ((uint32_t)((wn * 32 + (lane & 7) + ((lane & 16) ? 8 : 0)) * DSASX +
                    ((lane & 8) ? 8 : 0))) * 2;

    float acc[4][4][4];
#pragma unroll
    for (int mt = 0; mt < 4; mt++)
#pragma unroll
        for (int nt = 0; nt < 4; nt++)
#pragma unroll
            for (int r = 0; r < 4; r++) acc[mt][nt][r] = 0.f;

#pragma unroll
    for (int ks = 0; ks < 3; ks++) {
        const uint32_t kb2 = (uint32_t)(ks * 16) * 2;
        uint32_t a[4][4], b[4][2];
#pragma unroll
        for (int mt = 0; mt < 4; mt++)
            ldsm_x4(a[mt][0], a[mt][1], a[mt][2], a[mt][3],
                    sAb + laneA + (uint32_t)(mt * 16 * DSASX) * 2 + kb2);
#pragma unroll
        for (int p = 0; p < 2; p++)
            ldsm_x4(b[2 * p][0], b[2 * p][1], b[2 * p + 1][0], b[2 * p + 1][1],
                    sBb + laneB + (uint32_t)(p * 16 * DSASX) * 2 + kb2);
#pragma unroll
        for (int mt = 0; mt < 4; mt++)
#pragma unroll
            for (int nt = 0; nt < 4; nt++)
                MMA_F16(acc[mt][nt], a[mt], b[nt]);
    }

#pragma unroll
    for (int mt = 0; mt < 4; mt++) {
        const int m0 = bm + wm * 64 + mt * 16 + gr;
#pragma unroll
        for (int half = 0; half < 2; half++) {
            const int m = m0 + half * 8;
#pragma unroll
            for (int nt = 0; nt < 4; nt++) {
                const int nbase = bn + wn * 32 + nt * 8 + 2 * tq;
#pragma unroll
                for (int j = 0; j < 2; j++) {
                    const int n = nbase + j;
                    float v = acc[mt][nt][half * 2 + j] + bias[n];
                    v = (v > 20.f) ? v : log1pf(__expf(v));
                    Cc[(size_t)m * DINNER + n] = v;
                }
            }
        }
    }
}

// ---------------------------------------------------------------------------
// Fused init: 9 fp16-conversion slices (f/b out_w packed into g_wcat).
// ---------------------------------------------------------------------------
__global__ void init_kernel(const float4* __restrict__ x,
                            const float4* __restrict__ fiw, const float4* __restrict__ biw,
                            const float4* __restrict__ fow, const float4* __restrict__ bow,
                            const float4* __restrict__ fxp, const float4* __restrict__ bxp,
                            const float4* __restrict__ fdw, const float4* __restrict__ bdw)
{
    const float4* src; __half* hdst; int n4;
    bool cat = false; int catoff = 0;
    switch (blockIdx.y) {
        case 0:  src = x;   hdst = g_xr;     n4 = MTOT * DMODEL / 4;    break;
        case 1:  src = fiw; hdst = g_win[0]; n4 = XZW * DMODEL / 4;     break;
        case 2:  src = biw; hdst = g_win[1]; n4 = XZW * DMODEL / 4;     break;
        case 3:  src = fow; hdst = g_wcat;   n4 = DMODEL * DINNER / 4;
                 cat = true; catoff = 0;                                break;
        case 4:  src = bow; hdst = g_wcat;   n4 = DMODEL * DINNER / 4;
                 cat = true; catoff = DINNER;                           break;
        case 5:  src = fxp; hdst = g_wxp[0]; n4 = XDBLW * DINNER / 4;   break;
        case 6:  src = bxp; hdst = g_wxp[1]; n4 = XDBLW * DINNER / 4;   break;
        case 7:  src = fdw; hdst = g_wdt[0]; n4 = DINNER * DTRANK / 4;  break;
        default: src = bdw; hdst = g_wdt[1]; n4 = DINNER * DTRANK / 4;  break;
    }
    for (int i = blockIdx.x * blockDim.x + threadIdx.x; i < n4;
         i += gridDim.x * blockDim.x) {
        float4 v = src[i];
        size_t di = (size_t)i * 4;
        if (cat) {
            const int row = (int)(di / DINNER);
            const int col = (int)(di - (size_t)row * DINNER);
            di = (size_t)row * XZW + catoff + col;
        }
        __half2* d2 = reinterpret_cast<__half2*>(hdst + di);
        d2[0] = __floats2half2_rn(v.x, v.y);
        d2[1] = __floats2half2_rn(v.z, v.w);
    }
}

// ---------------------------------------------------------------------------
// Causal depthwise conv (D_CONV=4) + bias + SiLU, l-tiled x4.
// ---------------------------------------------------------------------------
__global__ void conv_silu_kernel(const float* __restrict__ f_conv_w,
                                 const float* __restrict__ f_conv_b,
                                 const float* __restrict__ b_conv_w,
                                 const float* __restrict__ b_conv_b)
{
    const int dir = blockIdx.y;
    const float* conv_w = dir ? b_conv_w : f_conv_w;
    const float* conv_b = dir ? b_conv_b : f_conv_b;

    const int NCH = DINNER / 4;
    const int idx = blockIdx.x * blockDim.x + threadIdx.x;
    if (idx >= (MTOT / 4) * NCH) return;
    const int rt   = idx / NCH;
    const int d4   = (idx - rt * NCH) * 4;
    const int row0 = rt * 4;
    const int l0   = row0 & (SEQL - 1);

    const float* xz = g_xz[dir];
    float cw[4][4];
#pragma unroll
    for (int j = 0; j < 4; j++) {
        const float4 w = *(const float4*)(conv_w + (d4 + j) * DCONV);
        cw[j][0] = w.x; cw[j][1] = w.y; cw[j][2] = w.z; cw[j][3] = w.w;
    }

    float4 xv[7];
#pragma unroll
    for (int j = 0; j < 7; j++) {
        const int l = l0 - 3 + j;
        xv[j] = (l >= 0)
              ? *(const float4*)(xz + (size_t)(row0 - 3 + j) * XZW + d4)
              : make_float4(0.f, 0.f, 0.f, 0.f);
    }
    const float4 bias = *(const float4*)(conv_b + d4);

#pragma unroll
    for (int i = 0; i < 4; i++) {
        float4 s = bias;
#pragma unroll
        for (int k = 0; k < 4; k++) {
            const float4 xvv = xv[i + k];
            s.x = fmaf(cw[0][k], xvv.x, s.x);
            s.y = fmaf(cw[1][k], xvv.y, s.y);
            s.z = fmaf(cw[2][k], xvv.z, s.z);
            s.w = fmaf(cw[3][k], xvv.w, s.w);
        }
        float4 o;
        o.x = s.x / (1.f + __expf(-s.x));
        o.y = s.y / (1.f + __expf(-s.y));
        o.z = s.z / (1.f + __expf(-s.z));
        o.w = s.w / (1.f + __expf(-s.w));
        *(float4*)(g_u[dir] + (size_t)(row0 + i) * DINNER + d4) = o;
        __half2* h2 = reinterpret_cast<__half2*>(g_ur[dir] + (size_t)(row0 + i) * DINNER + d4);
        h2[0] = __floats2half2_rn(o.x, o.y);
        h2[1] = __floats2half2_rn(o.z, o.w);
    }
}

// ---------------------------------------------------------------------------
// Selective scan — unroll 8, group double-buffered; dir1 output pre-flipped.
// Output written into the concat buffer g_yall[m][dir*1536 + d] (fp16).
// ---------------------------------------------------------------------------
#define UNR   8
#define NGRP  (SEQL / UNR)

__global__ __launch_bounds__(128)
void scan_kernel(const float* __restrict__ fAlog, const float* __restrict__ fD,
                 const float* __restrict__ bAlog, const float* __restrict__ bD)
{
    const int dir = blockIdx.y;
    const float* Alog = dir ? bAlog : fAlog;
    const float* Dp   = dir ? bD    : fD;
    const float* delta = g_delta[dir];
    const float* u     = g_u[dir];
    const float* xdbl  = g_xdbl[dir];
    const float* xz    = g_xz[dir];

    const int lane = threadIdx.x & 31;
    const int warp = threadIdx.x >> 5;
    const int half = lane >> 4;
    const int n    = lane & 15;

    const int c = blockIdx.x * 8 + warp * 2 + half;
    const int b = c / DINNER;
    const int d = c - b * DINNER;

    const float Aneg = -__expf(Alog[d * DSTATE + n]);
    const float Dd   = Dp[d];
    const bool  ln0  = (n == 0);

    const size_t rowbase = (size_t)b * SEQL;
    const float* pDl = delta + rowbase * DINNER + d;
    const float* pU  = u     + rowbase * DINNER + d;
    const float* pB  = xdbl  + rowbase * XDBLW + DTRANK + n;
    const float* pC  = pB + DSTATE;
    const float* pZ  = xz    + rowbase * XZW + DINNER + d;
    __half* yout = g_yall + (size_t)dir * DINNER + d;

    float cdl[UNR], cuu[UNR], cBn[UNR], cCn[UNR], czz[UNR];

    auto load_grp = [&](int g, float* adl, float* auu, float* aBn,
                        float* aCn, float* azz) {
        const int l0 = g * UNR;
#pragma unroll
        for (int i = 0; i < UNR; i++) {
            adl[i] = pDl[(size_t)(l0 + i) * DINNER];
            auu[i] = pU [(size_t)(l0 + i) * DINNER];
            aBn[i] = pB [(size_t)(l0 + i) * XDBLW];
            aCn[i] = pC [(size_t)(l0 + i) * XDBLW];
        }
        if (ln0) {
#pragma unroll
            for (int i = 0; i < UNR; i++)
                azz[i] = pZ[(size_t)(l0 + i) * XZW];
        }
    };

    load_grp(0, cdl, cuu, cBn, cCn, czz);
    float h = 0.f;

    for (int g = 0; g < NGRP; g++) {
        float ndl[UNR], nuu[UNR], nBn[UNR], nCn[UNR], nzz[UNR];
        load_grp((g + 1 < NGRP) ? (g + 1) : 0, ndl, nuu, nBn, nCn, nzz);

        float dA[UNR];
#pragma unroll
        for (int i = 0; i < UNR; i++) dA[i] = __expf(cdl[i] * Aneg);

        float yp[UNR];
#pragma unroll
        for (int i = 0; i < UNR; i++) {
            h = fmaf(dA[i], h, cdl[i] * cBn[i] * cuu[i]);
            yp[i] = h * cCn[i];
        }

#pragma unroll
        for (int s = 1; s <= 8; s <<= 1) {
#pragma unroll
            for (int i = 0; i < UNR; i++)
                yp[i] += __shfl_xor_sync(0xffffffffu, yp[i], s);
        }

        if (ln0) {
            const int l0 = g * UNR;
#pragma unroll
            for (int i = 0; i < UNR; i++) {
                float y = fmaf(cuu[i], Dd, yp[i]);
                const float zz = czz[i];
                y *= zz / (1.f + __expf(-zz));
                const size_t row  = rowbase + l0 + i;
                const size_t orow = dir ? (row ^ (SEQL - 1)) : row;
                yout[orow * XZW] = __float2half_rn(y);
            }
        }

#pragma unroll
        for (int i = 0; i < UNR; i++) {
            cdl[i] = ndl[i]; cuu[i] = nuu[i];
            cBn[i] = nBn[i]; cCn[i] = nCn[i]; czz[i] = nzz[i];
        }
    }
}

// ---------------------------------------------------------------------------
// Host launch.
// ---------------------------------------------------------------------------
extern "C" void kernel_launch(void* const* d_in, const int* in_sizes, int n_in,
                              void* d_out, int out_size)
{
    const float* x = (const float*)d_in[0];
    float* out = (float*)d_out;

    const float* f_in_w    = (const float*)d_in[1];
    const float* f_conv_w  = (const float*)d_in[2];
    const float* f_conv_b  = (const float*)d_in[3];
    const float* f_xproj_w = (const float*)d_in[4];
    const float* f_dt_w    = (const float*)d_in[5];
    const float* f_dt_b    = (const float*)d_in[6];
    const float* f_Alog    = (const float*)d_in[7];
    const float* f_D       = (const float*)d_in[8];
    const float* f_out_w   = (const float*)d_in[9];
    const float* b_in_w    = (const float*)d_in[10];
    const float* b_conv_w  = (const float*)d_in[11];
    const float* b_conv_b  = (const float*)d_in[12];
    const float* b_xproj_w = (const float*)d_in[13];
    const float* b_dt_w    = (const float*)d_in[14];
    const float* b_dt_b    = (const float*)d_in[15];
    const float* b_Alog    = (const float*)d_in[16];
    const float* b_D       = (const float*)d_in[17];
    const float* b_out_w   = (const float*)d_in[18];

    // device-global fp32 targets
    float* xz0;    float* xz1;
    float* xpart0; float* xpart1;
    float* opart0; float* opart1;
    cudaGetSymbolAddress((void**)&xz0,    g_xz);
    xz1    = xz0    + (size_t)MTOT * XZW;
    cudaGetSymbolAddress((void**)&xpart0, g_xpart);
    xpart1 = xpart0 + (size_t)NSPLIT * MTOT * XDBLW;
    cudaGetSymbolAddress((void**)&opart0, g_opart);
    opart1 = opart0 + (size_t)MTOT * DMODEL;

    cudaFuncSetAttribute(gemm_h<true>,
                         cudaFuncAttributeMaxDynamicSharedMemorySize, SMEM_BK64);
    cudaFuncSetAttribute(gemm_h<false>,
                         cudaFuncAttributeMaxDynamicSharedMemorySize, SMEM_BK64);

    // init: fp16 conversion of all GEMM operands (out_w packed f|b)
    init_kernel<<<dim3(160, 9), 256>>>(
        (const float4*)x,
        (const float4*)f_in_w,    (const float4*)b_in_w,
        (const float4*)f_out_w,   (const float4*)b_out_w,
        (const float4*)f_xproj_w, (const float4*)b_xproj_w,
        (const float4*)f_dt_w,    (const float4*)b_dt_w);

    // in_proj: xz = x(flip dir1) @ in_w^T   [2048,3072], K=768
    gemm_h<true><<<dim3(XZW / 128, MTOT / 128, 2), 256, SMEM_BK64>>>(
        HBUF_XR, HBUF_WIN, nullptr, xz0, xz1, 0,
        XZW, DMODEL, DMODEL, XZW, XZW / 128, DMODEL);

    // depthwise conv + SiLU
    conv_silu_kernel<<<dim3(((MTOT / 4) * (DINNER / 4) + 255) / 256, 2), 256>>>(
        f_conv_w, f_conv_b, b_conv_w, b_conv_b);

    // x_proj split-K x8 -> per-split partials (no atomics)
    gemm_h<false><<<dim3(NSPLIT, MTOT / 128, 2), 256, SMEM_BK64>>>(
        HBUF_UR, HBUF_WXP, nullptr, xpart0, xpart1, (long)MTOT * XDBLW,
        XDBLW, DINNER, DINNER, XDBLW, 1, DINNER / NSPLIT);

    // deterministic reduce of the 8 partials -> xdbl
    reduce_xdbl_kernel<<<dim3((MTOT * XDBLW / 4 + 255) / 256, 2), 256>>>();

    // delta: softplus(dt @ dt_w^T + dt_b)  [2048,1536], K=48
    gemm_delta<<<dim3(DINNER / 128, MTOT / 128, 2), 256>>>(f_dt_b, b_dt_b);

    // selective scan (writes concat ypre buffer, dir1 pre-flipped)
    scan_kernel<<<dim3((NB * DINNER) / 8, 2), 128>>>(f_Alog, f_D, b_Alog, b_D);

    // out_proj: concat-K GEMM [2048,768], K=3072, split-K x2 -> partials
    gemm_h<false><<<dim3(2 * (DMODEL / 128), MTOT / 128, 1), 256, SMEM_BK64>>>(
        HBUF_YALL, HBUF_WCAT, nullptr, opart0, nullptr, (long)MTOT * DMODEL,
        DMODEL, XZW, XZW, DMODEL, DMODEL / 128, XZW / 2);

    // out = part0 + part1
    add_out_kernel<<<(MTOT * DMODEL / 4 + 255) / 256, 256>>>((float4*)out);
}

// round 14
// speedup vs baseline: 1.0110x; 1.0110x over previous
#include <cuda_runtime.h>
#include <cuda_bf16.h>
#include <cuda_fp16.h>
#include <cstdint>

// ---------------------------------------------------------------------------
// BidirectionalMambaLayer — Round 14: occupancy-oriented fp16 GEMM.
// CTA tile 128x64, warp tile 32x32 (8 warps 4m x 2n), 3 CTAs/SM target.
// Graph structure reverted to round 12 (atomics + zero-init, best = 457us).
// Numerics identical (rel_err 5.116e-4).
// ---------------------------------------------------------------------------

#define SEQL   1024
#define NB     2
#define MTOT   (NB * SEQL)
#define DMODEL 768
#define DINNER 1536
#define DSTATE 16
#define DTRANK 48
#define DCONV  4
#define XZW    (2 * DINNER)            // 3072
#define XDBLW  (DTRANK + 2 * DSTATE)   // 80

// -------------------------- scratch (device globals) -----------------------
__device__ float  g_xz   [2][(size_t)MTOT * XZW];
__device__ float  g_u    [2][(size_t)MTOT * DINNER];  // exact (scan)
__device__ __half g_ur   [2][(size_t)MTOT * DINNER];  // fp16 (x_proj A)
__device__ float  g_xdbl [2][(size_t)MTOT * XDBLW];   // exact totals
__device__ float  g_delta[2][(size_t)MTOT * DINNER];
__device__ __half g_ypre [2][(size_t)MTOT * DINNER];  // fp16 (out_proj A)
__device__ __half g_xr   [(size_t)MTOT * DMODEL];     // fp16 x
__device__ __half g_win  [2][(size_t)XZW * DMODEL];
__device__ __half g_wxp  [2][(size_t)XDBLW * DINNER];
__device__ __half g_wdt  [2][(size_t)DINNER * DTRANK];
__device__ __half g_wout [2][(size_t)DMODEL * DINNER];

enum { HBUF_XR = 0, HBUF_UR, HBUF_YPRE,
       HBUF_WIN, HBUF_WXP, HBUF_WOUT };

__device__ __forceinline__ __half* scratch_h(int id, int dir) {
    switch (id) {
        case HBUF_XR:   return g_xr;
        case HBUF_UR:   return g_ur[dir];
        case HBUF_YPRE: return g_ypre[dir];
        case HBUF_WIN:  return g_win[dir];
        case HBUF_WXP:  return g_wxp[dir];
        case HBUF_WOUT: return g_wout[dir];
    }
    return nullptr;
}

__device__ __forceinline__ void cp16(uint32_t saddr, const __half* gptr, bool ok) {
    int sz = ok ? 16 : 0;
    asm volatile("cp.async.cg.shared.global [%0], [%1], 16, %2;"
                 :: "r"(saddr), "l"(gptr), "r"(sz));
}
__device__ __forceinline__ void cp_commit() { asm volatile("cp.async.commit_group;"); }
__device__ __forceinline__ void cp_wait0()  { asm volatile("cp.async.wait_group 0;"); }

__device__ __forceinline__ void ldsm_x4(uint32_t& r0, uint32_t& r1,
                                        uint32_t& r2, uint32_t& r3, uint32_t a) {
    asm volatile("ldmatrix.sync.aligned.m8n8.x4.shared.b16 {%0,%1,%2,%3}, [%4];"
                 : "=r"(r0), "=r"(r1), "=r"(r2), "=r"(r3) : "r"(a));
}

#define MMA_F16(acc, a, b)                                              \
    asm volatile(                                                       \
        "mma.sync.aligned.m16n8k16.row.col.f32.f16.f16.f32 "            \
        "{%0,%1,%2,%3}, {%4,%5,%6,%7}, {%8,%9}, {%0,%1,%2,%3};"         \
        : "+f"((acc)[0]), "+f"((acc)[1]), "+f"((acc)[2]), "+f"((acc)[3])\
        : "r"((a)[0]), "r"((a)[1]), "r"((a)[2]), "r"((a)[3]),           \
          "r"((b)[0]), "r"((b)[1]))

// ---------------------------------------------------------------------------
// fp16 mma.sync TN GEMM, CTA tile 128x64 (BM=128, BN=64), BK=64, STG=2,
// 256 threads (8 warps as 4m x 2n), warp tile 32x32. Dir-merged, split-K,
// optional atomic epilogue. Targets 3 CTAs/SM (smem 55.3KB, ~80 regs).
// ---------------------------------------------------------------------------
#define GBK   64
#define GBN   64
#define GSASX 72                           // 64 + 8 halves pad
#define STA_BYTES (128 * GSASX * 2)        // 18432
#define STB_BYTES (GBN * GSASX * 2)        //  9216
#define SMEM_G (2 * (STA_BYTES + STB_BYTES))   // 55296 B

template<bool FLIPA1, bool ATOMIC>
__global__ __launch_bounds__(256, 3)
void gemm_h(int aId, int bId,
            float* __restrict__ Cext, float* __restrict__ Cd0, float* __restrict__ Cd1,
            int N, int K, int lda, int ldc, int nxt, int kchunk)
{
    const int dir = blockIdx.z;
    const __half* A = scratch_h(aId, dir);
    const __half* W = scratch_h(bId, dir);
    float*        C = Cext ? Cext : (dir ? Cd1 : Cd0);

    const int split = blockIdx.x / nxt;
    const int bn    = (blockIdx.x - split * nxt) * GBN;
    const int bm    = blockIdx.y * 128;
    const int kbeg  = split * kchunk;
    const int T     = kchunk / GBK;

    extern __shared__ __half dynsmem_h[];

    const int tid  = threadIdx.x;
    const int lane = tid & 31;
    const int warp = tid >> 5;
    const int wm   = warp >> 1;        // 0..3 (m)
    const int wn   = warp & 1;         // 0..1 (n)
    const int gr   = lane >> 2;
    const int tq   = lane & 3;

    const uint32_t sAb = (uint32_t)__cvta_generic_to_shared(dynsmem_h);
    const uint32_t sBb = sAb + 2 * STA_BYTES;

    // ldsm lane addresses (bytes)
    const uint32_t laneA =
        ((uint32_t)((wm * 32 + (lane & 15)) * GSASX + (lane >> 4) * 8)) * 2;
    const uint32_t laneB =
        ((uint32_t)((wn * 32 + (lane & 7) + ((lane & 16) ? 8 : 0)) * GSASX +
                    ((lane & 8) ? 8 : 0))) * 2;

    // cp.async chunk geometry: A 128x8 chunks (4 iters), B 64x8 chunks (2 iters)
    const int arow = tid >> 1;                 // rows via 2 chunks/thread? no:
    // A: 1024 chunks -> thread handles chunks tid, tid+256, tid+512, tid+768
    // B: 512 chunks  -> thread handles chunks tid, tid+256

    auto load_tile = [&](int t, int st) {
        const int kof = kbeg + t * GBK;
#pragma unroll
        for (int i = 0; i < 4; i++) {
            const int c = tid + i * 256;
            const int r = c >> 3, q = (c & 7) * 8;
            int gm = bm + r;
            if (FLIPA1 && dir) gm ^= (SEQL - 1);
            cp16(sAb + st * STA_BYTES + (uint32_t)(r * GSASX + q) * 2,
                 A + (size_t)gm * lda + kof + q, true);
        }
#pragma unroll
        for (int i = 0; i < 2; i++) {
            const int c = tid + i * 256;
            const int r = c >> 3, q = (c & 7) * 8;
            const int wr = bn + r;
            cp16(sBb + st * STB_BYTES + (uint32_t)(r * GSASX + q) * 2,
                 W + (size_t)wr * K + kof + q, wr < N);
        }
        cp_commit();
    };

    float acc[2][4][4];
#pragma unroll
    for (int mt = 0; mt < 2; mt++)
#pragma unroll
        for (int nt = 0; nt < 4; nt++)
#pragma unroll
            for (int r = 0; r < 4; r++) acc[mt][nt][r] = 0.f;

    load_tile(0, 0);

    for (int t = 0; t < T; t++) {
        const int st = t & 1;
        cp_wait0();
        __syncthreads();

        if (t + 1 < T) load_tile(t + 1, st ^ 1);

        const uint32_t aAddr = sAb + st * STA_BYTES + laneA;
        const uint32_t bAddr = sBb + st * STB_BYTES + laneB;

        // fragment double buffer across k-steps
        uint32_t a[2][2][4], b[2][4][2];
#pragma unroll
        for (int mt = 0; mt < 2; mt++)
            ldsm_x4(a[0][mt][0], a[0][mt][1], a[0][mt][2], a[0][mt][3],
                    aAddr + (uint32_t)(mt * 16 * GSASX) * 2);
        ldsm_x4(b[0][0][0], b[0][0][1], b[0][1][0], b[0][1][1], bAddr);
        ldsm_x4(b[0][2][0], b[0][2][1], b[0][3][0], b[0][3][1],
                bAddr + (uint32_t)(16 * GSASX) * 2);

#pragma unroll
        for (int ks = 0; ks < GBK / 16; ks++) {
            const int cur = ks & 1;
            if (ks + 1 < GBK / 16) {
                const int nb = cur ^ 1;
                const uint32_t kb2 = (uint32_t)((ks + 1) * 16) * 2;
#pragma unroll
                for (int mt = 0; mt < 2; mt++)
                    ldsm_x4(a[nb][mt][0], a[nb][mt][1], a[nb][mt][2], a[nb][mt][3],
                            aAddr + (uint32_t)(mt * 16 * GSASX) * 2 + kb2);
                ldsm_x4(b[nb][0][0], b[nb][0][1], b[nb][1][0], b[nb][1][1],
                        bAddr + kb2);
                ldsm_x4(b[nb][2][0], b[nb][2][1], b[nb][3][0], b[nb][3][1],
                        bAddr + (uint32_t)(16 * GSASX) * 2 + kb2);
            }
#pragma unroll
            for (int mt = 0; mt < 2; mt++)
#pragma unroll
                for (int nt = 0; nt < 4; nt++)
                    MMA_F16(acc[mt][nt], a[cur][mt], b[cur][nt]);
        }
    }

    // epilogue
#pragma unroll
    for (int mt = 0; mt < 2; mt++) {
        const int m0 = bm + wm * 32 + mt * 16 + gr;
#pragma unroll
        for (int half = 0; half < 2; half++) {
            const int m = m0 + half * 8;
#pragma unroll
            for (int nt = 0; nt < 4; nt++) {
                const int nbase = bn + wn * 32 + nt * 8 + 2 * tq;
#pragma unroll
                for (int j = 0; j < 2; j++) {
                    const int n = nbase + j;
                    if (n < N) {
                        const float v = acc[mt][nt][half * 2 + j];
                        if (ATOMIC) atomicAdd(&C[(size_t)m * ldc + n], v);
                        else        C[(size_t)m * ldc + n] = v;
                    }
                }
            }
        }
    }
}

// ---------------------------------------------------------------------------
// Fused small-K delta GEMM: delta = softplus(dt @ dt_w^T + dt_b), K=48.
// (128x128 tile, 64x32 warp tile — unchanged from round 12.)
// ---------------------------------------------------------------------------
#define DSASX 56    // 48 + 8 pad
__global__ __launch_bounds__(256, 2)
void gemm_delta(const float* __restrict__ dt_b0, const float* __restrict__ dt_b1)
{
    const int dir = blockIdx.z;
    const float*  Xd = g_xdbl[dir];
    const __half* W  = g_wdt[dir];
    const float*  bias = dir ? dt_b1 : dt_b0;
    float*        Cc = g_delta[dir];

    __shared__ __half sA[128 * DSASX];
    __shared__ __half sB[128 * DSASX];

    const int bn = blockIdx.x * 128;
    const int bm = blockIdx.y * 128;

    const int tid  = threadIdx.x;
    const int lane = tid & 31;
    const int warp = tid >> 5;
    const int wm   = warp >> 2;
    const int wn   = warp & 3;
    const int gr   = lane >> 2;
    const int tq   = lane & 3;

    const uint32_t sAb = (uint32_t)__cvta_generic_to_shared(sA);
    const uint32_t sBb = (uint32_t)__cvta_generic_to_shared(sB);

#pragma unroll
    for (int i = 0; i < 3; i++) {
        const int c = tid + i * 256;
        const int r = c / 6, q = (c - r * 6) * 8;
        cp16(sBb + (uint32_t)(r * DSASX + q) * 2, W + (size_t)(bn + r) * DTRANK + q, true);
    }
    cp_commit();

#pragma unroll
    for (int i = 0; i < 6; i++) {
        const int c = tid + i * 256;
        const int r = c / 12, q = (c - r * 12) * 4;
        const float4 v = *(const float4*)(Xd + (size_t)(bm + r) * XDBLW + q);
        __half2* d2 = reinterpret_cast<__half2*>(&sA[r * DSASX + q]);
        d2[0] = __floats2half2_rn(v.x, v.y);
        d2[1] = __floats2half2_rn(v.z, v.w);
    }
    cp_wait0();
    __syncthreads();

    const uint32_t laneA =
        ((uint32_t)((wm * 64 + (lane & 15)) * DSASX + (lane >> 4) * 8)) * 2;
    const uint32_t laneB =
        ((uint32_t)((wn * 32 + (lane & 7) + ((lane & 16) ? 8 : 0)) * DSASX +
                    ((lane & 8) ? 8 : 0))) * 2;

    float acc[4][4][4];
#pragma unroll
    for (int mt = 0; mt < 4; mt++)
#pragma unroll
        for (int nt = 0; nt < 4; nt++)
#pragma unroll
            for (int r = 0; r < 4; r++) acc[mt][nt][r] = 0.f;

#pragma unroll
    for (int ks = 0; ks < 3; ks++) {
        const uint32_t kb2 = (uint32_t)(ks * 16) * 2;
        uint32_t a[4][4], b[4][2];
#pragma unroll
        for (int mt = 0; mt < 4; mt++)
            ldsm_x4(a[mt][0], a[mt][1], a[mt][2], a[mt][3],
                    sAb + laneA + (uint32_t)(mt * 16 * DSASX) * 2 + kb2);
#pragma unroll
        for (int p = 0; p < 2; p++)
            ldsm_x4(b[2 * p][0], b[2 * p][1], b[2 * p + 1][0], b[2 * p + 1][1],
                    sBb + laneB + (uint32_t)(p * 16 * DSASX) * 2 + kb2);
#pragma unroll
        for (int mt = 0; mt < 4; mt++)
#pragma unroll
            for (int nt = 0; nt < 4; nt++)
                MMA_F16(acc[mt][nt], a[mt], b[nt]);
    }

#pragma unroll
    for (int mt = 0; mt < 4; mt++) {
        const int m0 = bm + wm * 64 + mt * 16 + gr;
#pragma unroll
        for (int half = 0; half < 2; half++) {
            const int m = m0 + half * 8;
#pragma unroll
            for (int nt = 0; nt < 4; nt++) {
                const int nbase = bn + wn * 32 + nt * 8 + 2 * tq;
#pragma unroll
                for (int j = 0; j < 2; j++) {
                    const int n = nbase + j;
                    float v = acc[mt][nt][half * 2 + j] + bias[n];
                    v = (v > 20.f) ? v : log1pf(__expf(v));
                    Cc[(size_t)m * DINNER + n] = v;
                }
            }
        }
    }
}

// ---------------------------------------------------------------------------
// Fused init: zero(out), zero(xdbl x2), + 9 fp16-conversion slices.
// ---------------------------------------------------------------------------
__global__ void init_kernel(float4* __restrict__ out4,
                            const float4* __restrict__ x,
                            const float4* __restrict__ fiw, const float4* __restrict__ biw,
                            const float4* __restrict__ fow, const float4* __restrict__ bow,
                            const float4* __restrict__ fxp, const float4* __restrict__ bxp,
                            const float4* __restrict__ fdw, const float4* __restrict__ bdw)
{
    const float4* src = nullptr; __half* hdst = nullptr; float4* zdst = nullptr; int n4;
    switch (blockIdx.y) {
        case 0:  zdst = out4;               n4 = MTOT * DMODEL / 4;    break;
        case 1:  zdst = (float4*)g_xdbl[0]; n4 = MTOT * XDBLW / 4;     break;
        case 2:  zdst = (float4*)g_xdbl[1]; n4 = MTOT * XDBLW / 4;     break;
        case 3:  src = x;   hdst = g_xr;      n4 = MTOT * DMODEL / 4;   break;
        case 4:  src = fiw; hdst = g_win[0];  n4 = XZW * DMODEL / 4;    break;
        case 5:  src = biw; hdst = g_win[1];  n4 = XZW * DMODEL / 4;    break;
        case 6:  src = fow; hdst = g_wout[0]; n4 = DMODEL * DINNER / 4; break;
        case 7:  src = bow; hdst = g_wout[1]; n4 = DMODEL * DINNER / 4; break;
        case 8:  src = fxp; hdst = g_wxp[0];  n4 = XDBLW * DINNER / 4;  break;
        case 9:  src = bxp; hdst = g_wxp[1];  n4 = XDBLW * DINNER / 4;  break;
        case 10: src = fdw; hdst = g_wdt[0];  n4 = DINNER * DTRANK / 4; break;
        default: src = bdw; hdst = g_wdt[1];  n4 = DINNER * DTRANK / 4; break;
    }
    if (src == nullptr) {
        for (int i = blockIdx.x * blockDim.x + threadIdx.x; i < n4;
             i += gridDim.x * blockDim.x)
            zdst[i] = make_float4(0.f, 0.f, 0.f, 0.f);
    } else {
        __half2* d2 = reinterpret_cast<__half2*>(hdst);
        for (int i = blockIdx.x * blockDim.x + threadIdx.x; i < n4;
             i += gridDim.x * blockDim.x) {
            float4 v = src[i];
            d2[2 * i + 0] = __floats2half2_rn(v.x, v.y);
            d2[2 * i + 1] = __floats2half2_rn(v.z, v.w);
        }
    }
}

// ---------------------------------------------------------------------------
// Causal depthwise conv (D_CONV=4) + bias + SiLU, l-tiled x4.
// ---------------------------------------------------------------------------
__global__ void conv_silu_kernel(const float* __restrict__ f_conv_w,
                                 const float* __restrict__ f_conv_b,
                                 const float* __restrict__ b_conv_w,
                                 const float* __restrict__ b_conv_b)
{
    const int dir = blockIdx.y;
    const float* conv_w = dir ? b_conv_w : f_conv_w;
    const float* conv_b = dir ? b_conv_b : f_conv_b;

    const int NCH = DINNER / 4;
    const int idx = blockIdx.x * blockDim.x + threadIdx.x;
    if (idx >= (MTOT / 4) * NCH) return;
    const int rt   = idx / NCH;
    const int d4   = (idx - rt * NCH) * 4;
    const int row0 = rt * 4;
    const int l0   = row0 & (SEQL - 1);

    const float* xz = g_xz[dir];
    float cw[4][4];
#pragma unroll
    for (int j = 0; j < 4; j++) {
        const float4 w = *(const float4*)(conv_w + (d4 + j) * DCONV);
        cw[j][0] = w.x; cw[j][1] = w.y; cw[j][2] = w.z; cw[j][3] = w.w;
    }

    float4 xv[7];
#pragma unroll
    for (int j = 0; j < 7; j++) {
        const int l = l0 - 3 + j;
        xv[j] = (l >= 0)
              ? *(const float4*)(xz + (size_t)(row0 - 3 + j) * XZW + d4)
              : make_float4(0.f, 0.f, 0.f, 0.f);
    }
    const float4 bias = *(const float4*)(conv_b + d4);

#pragma unroll
    for (int i = 0; i < 4; i++) {
        float4 s = bias;
#pragma unroll
        for (int k = 0; k < 4; k++) {
            const float4 xvv = xv[i + k];
            s.x = fmaf(cw[0][k], xvv.x, s.x);
            s.y = fmaf(cw[1][k], xvv.y, s.y);
            s.z = fmaf(cw[2][k], xvv.z, s.z);
            s.w = fmaf(cw[3][k], xvv.w, s.w);
        }
        float4 o;
        o.x = s.x / (1.f + __expf(-s.x));
        o.y = s.y / (1.f + __expf(-s.y));
        o.z = s.z / (1.f + __expf(-s.z));
        o.w = s.w / (1.f + __expf(-s.w));
        *(float4*)(g_u[dir] + (size_t)(row0 + i) * DINNER + d4) = o;
        __half2* h2 = reinterpret_cast<__half2*>(g_ur[dir] + (size_t)(row0 + i) * DINNER + d4);
        h2[0] = __floats2half2_rn(o.x, o.y);
        h2[1] = __floats2half2_rn(o.z, o.w);
    }
}

// ---------------------------------------------------------------------------
// Selective scan — unroll 8, group double-buffered. dir1 output pre-flipped.
// ---------------------------------------------------------------------------
#define UNR   8
#define NGRP  (SEQL / UNR)

__global__ __launch_bounds__(128)
void scan_kernel(const float* __restrict__ fAlog, const float* __restrict__ fD,
                 const float* __restrict__ bAlog, const float* __restrict__ bD)
{
    const int dir = blockIdx.y;
    const float* Alog = dir ? bAlog : fAlog;
    const float* Dp   = dir ? bD    : fD;
    const float* delta = g_delta[dir];
    const float* u     = g_u[dir];
    const float* xdbl  = g_xdbl[dir];
    const float* xz    = g_xz[dir];
    __half*      ypre  = g_ypre[dir];

    const int lane = threadIdx.x & 31;
    const int warp = threadIdx.x >> 5;
    const int half = lane >> 4;
    const int n    = lane & 15;

    const int c = blockIdx.x * 8 + warp * 2 + half;
    const int b = c / DINNER;
    const int d = c - b * DINNER;

    const float Aneg = -__expf(Alog[d * DSTATE + n]);
    const float Dd   = Dp[d];
    const bool  ln0  = (n == 0);

    const size_t rowbase = (size_t)b * SEQL;
    const float* pDl = delta + rowbase * DINNER + d;
    const float* pU  = u     + rowbase * DINNER + d;
    const float* pB  = xdbl  + rowbase * XDBLW + DTRANK + n;
    const float* pC  = pB + DSTATE;
    const float* pZ  = xz    + rowbase * XZW + DINNER + d;

    float cdl[UNR], cuu[UNR], cBn[UNR], cCn[UNR], czz[UNR];

    auto load_grp = [&](int g, float* adl, float* auu, float* aBn,
                        float* aCn, float* azz) {
        const int l0 = g * UNR;
#pragma unroll
        for (int i = 0; i < UNR; i++) {
            adl[i] = pDl[(size_t)(l0 + i) * DINNER];
            auu[i] = pU [(size_t)(l0 + i) * DINNER];
            aBn[i] = pB [(size_t)(l0 + i) * XDBLW];
            aCn[i] = pC [(size_t)(l0 + i) * XDBLW];
        }
        if (ln0) {
#pragma unroll
            for (int i = 0; i < UNR; i++)
                azz[i] = pZ[(size_t)(l0 + i) * XZW];
        }
    };

    load_grp(0, cdl, cuu, cBn, cCn, czz);
    float h = 0.f;

    for (int g = 0; g < NGRP; g++) {
        float ndl[UNR], nuu[UNR], nBn[UNR], nCn[UNR], nzz[UNR];
        load_grp((g + 1 < NGRP) ? (g + 1) : 0, ndl, nuu, nBn, nCn, nzz);

        float dA[UNR];
#pragma unroll
        for (int i = 0; i < UNR; i++) dA[i] = __expf(cdl[i] * Aneg);

        float yp[UNR];
#pragma unroll
        for (int i = 0; i < UNR; i++) {
            h = fmaf(dA[i], h, cdl[i] * cBn[i] * cuu[i]);
            yp[i] = h * cCn[i];
        }

#pragma unroll
        for (int s = 1; s <= 8; s <<= 1) {
#pragma unroll
            for (int i = 0; i < UNR; i++)
                yp[i] += __shfl_xor_sync(0xffffffffu, yp[i], s);
        }

        if (ln0) {
            const int l0 = g * UNR;
#pragma unroll
            for (int i = 0; i < UNR; i++) {
                float y = fmaf(cuu[i], Dd, yp[i]);
                const float zz = czz[i];
                y *= zz / (1.f + __expf(-zz));
                const size_t row  = rowbase + l0 + i;
                const size_t orow = dir ? (row ^ (SEQL - 1)) : row;
                ypre[orow * DINNER + d] = __float2half_rn(y);
            }
        }

#pragma unroll
        for (int i = 0; i < UNR; i++) {
            cdl[i] = ndl[i]; cuu[i] = nuu[i];
            cBn[i] = nBn[i]; cCn[i] = nCn[i]; czz[i] = nzz[i];
        }
    }
}

// ---------------------------------------------------------------------------
// Host launch.
// ---------------------------------------------------------------------------
extern "C" void kernel_launch(void* const* d_in, const int* in_sizes, int n_in,
                              void* d_out, int out_size)
{
    const float* x = (const float*)d_in[0];
    float* out = (float*)d_out;

    const float* f_in_w    = (const float*)d_in[1];
    const float* f_conv_w  = (const float*)d_in[2];
    const float* f_conv_b  = (const float*)d_in[3];
    const float* f_xproj_w = (const float*)d_in[4];
    const float* f_dt_w    = (const float*)d_in[5];
    const float* f_dt_b    = (const float*)d_in[6];
    const float* f_Alog    = (const float*)d_in[7];
    const float* f_D       = (const float*)d_in[8];
    const float* f_out_w   = (const float*)d_in[9];
    const float* b_in_w    = (const float*)d_in[10];
    const float* b_conv_w  = (const float*)d_in[11];
    const float* b_conv_b  = (const float*)d_in[12];
    const float* b_xproj_w = (const float*)d_in[13];
    const float* b_dt_w    = (const float*)d_in[14];
    const float* b_dt_b    = (const float*)d_in[15];
    const float* b_Alog    = (const float*)d_in[16];
    const float* b_D       = (const float*)d_in[17];
    const float* b_out_w   = (const float*)d_in[18];

    // device-global fp32 targets
    float* xz0;   float* xz1;
    float* xdbl0; float* xdbl1;
    cudaGetSymbolAddress((void**)&xz0,   g_xz);
    xz1   = xz0   + (size_t)MTOT * XZW;
    cudaGetSymbolAddress((void**)&xdbl0, g_xdbl);
    xdbl1 = xdbl0 + (size_t)MTOT * XDBLW;

    cudaFuncSetAttribute(gemm_h<true,  false>,
                         cudaFuncAttributeMaxDynamicSharedMemorySize, SMEM_G);
    cudaFuncSetAttribute(gemm_h<false, true>,
                         cudaFuncAttributeMaxDynamicSharedMemorySize, SMEM_G);

    // fused init: zero out/xdbl + fp16 conversion of all GEMM operands
    init_kernel<<<dim3(160, 12), 256>>>(
        (float4*)out, (const float4*)x,
        (const float4*)f_in_w,    (const float4*)b_in_w,
        (const float4*)f_out_w,   (const float4*)b_out_w,
        (const float4*)f_xproj_w, (const float4*)b_xproj_w,
        (const float4*)f_dt_w,    (const float4*)b_dt_w);

    // in_proj: xz = x(flip dir1) @ in_w^T   [2048,3072], K=768
    gemm_h<true, false>
        <<<dim3(XZW / GBN, MTOT / 128, 2), 256, SMEM_G>>>(
        HBUF_XR, HBUF_WIN, nullptr, xz0, xz1,
        XZW, DMODEL, DMODEL, XZW, XZW / GBN, DMODEL);

    // depthwise conv + SiLU (writes u exact + u fp16)
    conv_silu_kernel<<<dim3(((MTOT / 4) * (DINNER / 4) + 255) / 256, 2), 256>>>(
        f_conv_w, f_conv_b, b_conv_w, b_conv_b);

    // x_proj (split-K x8, atomic): xdbl += u_h @ xproj_w^T   [2048,80], K=1536
    gemm_h<false, true>
        <<<dim3(8 * 2, MTOT / 128, 2), 256, SMEM_G>>>(
        HBUF_UR, HBUF_WXP, nullptr, xdbl0, xdbl1,
        XDBLW, DINNER, DINNER, XDBLW, 2, DINNER / 8);

    // delta: softplus(dt @ dt_w^T + dt_b)  [2048,1536], K=48 — fused small-K
    gemm_delta<<<dim3(DINNER / 128, MTOT / 128, 2), 256>>>(f_dt_b, b_dt_b);

    // selective scan (unroll-8 double-buffered; dir1 output pre-flipped)
    scan_kernel<<<dim3((NB * DINNER) / 8, 2), 128>>>(f_Alog, f_D, b_Alog, b_D);

    // out_proj (split-K x2, atomic): out += ypre_h @ out_w^T  [2048,768], K=1536
    gemm_h<false, true>
        <<<dim3((DMODEL / GBN) * 2, MTOT / 128, 2), 256, SMEM_G>>>(
        HBUF_YPRE, HBUF_WOUT, out, nullptr, nullptr,
        DMODEL, DINNER, DINNER, DMODEL, DMODEL / GBN, DINNER / 2);
}